// round 1
// baseline (speedup 1.0000x reference)
#include <cuda_runtime.h>

// Problem constants
namespace {
constexpr int kBT = 32;   // B*T = 4*8
constexpr int kL  = 512;
constexpr int kD  = 512;
constexpr int kH  = 8;
constexpr int kE  = 64;   // KD == VD
}

// Scratch (device globals: allocation-free per harness rules). 4 x 33.5 MB.
__device__ __align__(16) float g_Q[kBT * kH * kL * kE];
__device__ __align__(16) float g_K[kBT * kH * kL * kE];
__device__ __align__(16) float g_V[kBT * kH * kL * kE];
__device__ __align__(16) float g_A[kBT * kH * kL * kE];

// ---------------------------------------------------------------------------
// Kernel 1: projection GEMM.
// out[((bt*H + h)*L + l)*E + e] = sum_d X[bt][l][d] * W[d][h*E + e]
// Tile 64x64, BK=16, 256 threads, 4x4 microtile per thread.
// ---------------------------------------------------------------------------
__global__ __launch_bounds__(256)
void proj_kernel(const float* __restrict__ X, const float* __restrict__ W, int which)
{
    float* out = (which == 0) ? g_Q : (which == 1) ? g_K : g_V;

    const int h   = blockIdx.y;
    const int bt  = blockIdx.z;
    const int l0  = blockIdx.x * 64;
    const int tid = threadIdx.x;
    const int ty  = tid >> 4;
    const int tx  = tid & 15;

    __shared__ float As[64][17];   // [row][k] (padded: scalar broadcast reads)
    __shared__ float Bs[16][68];   // [k][col] (pad 68 keeps 16B alignment)

    const float* A  = X + ((size_t)bt * kL + l0) * kD;
    const float* Wp = W + h * kE;

    float acc[4][4] = {};

    const int ar = tid >> 2, aq = tid & 3;   // A tile: 64 rows x 4 float4
    const int bk = tid >> 4, bq = tid & 15;  // B tile: 16 rows x 16 float4

    for (int k0 = 0; k0 < kD; k0 += 16) {
        float4 av = *(const float4*)(A + (size_t)ar * kD + k0 + aq * 4);
        float4 bv = *(const float4*)(Wp + (size_t)(k0 + bk) * (kH * kE) + bq * 4);
        As[ar][aq * 4 + 0] = av.x;
        As[ar][aq * 4 + 1] = av.y;
        As[ar][aq * 4 + 2] = av.z;
        As[ar][aq * 4 + 3] = av.w;
        *(float4*)&Bs[bk][bq * 4] = bv;
        __syncthreads();

        #pragma unroll
        for (int k = 0; k < 16; k++) {
            float a0 = As[4 * ty + 0][k];
            float a1 = As[4 * ty + 1][k];
            float a2 = As[4 * ty + 2][k];
            float a3 = As[4 * ty + 3][k];
            float4 b = *(const float4*)&Bs[k][4 * tx];
            acc[0][0] += a0 * b.x; acc[0][1] += a0 * b.y; acc[0][2] += a0 * b.z; acc[0][3] += a0 * b.w;
            acc[1][0] += a1 * b.x; acc[1][1] += a1 * b.y; acc[1][2] += a1 * b.z; acc[1][3] += a1 * b.w;
            acc[2][0] += a2 * b.x; acc[2][1] += a2 * b.y; acc[2][2] += a2 * b.z; acc[2][3] += a2 * b.w;
            acc[3][0] += a3 * b.x; acc[3][1] += a3 * b.y; acc[3][2] += a3 * b.z; acc[3][3] += a3 * b.w;
        }
        __syncthreads();
    }

    float* O = out + ((size_t)(bt * kH + h) * kL + l0) * kE;
    #pragma unroll
    for (int i = 0; i < 4; i++) {
        *(float4*)(O + (size_t)(4 * ty + i) * kE + 4 * tx) =
            make_float4(acc[i][0], acc[i][1], acc[i][2], acc[i][3]);
    }
}

// ---------------------------------------------------------------------------
// Kernel 2: fused attention per (bt, h), 64 query rows per CTA, flash-style
// online softmax over 8 key tiles of 64.
// scores = (Q K^T * tau + delta) * (1/sqrt(64)) * mask[l][s]
// K tile is stored transposed with an XOR swizzle (col ^ (k & 60)) so both
// the transpose stores and the GEMM reads stay near conflict-free with
// stride-64 rows. Total static smem = 48 KB exactly.
// ---------------------------------------------------------------------------
__global__ __launch_bounds__(256)
void attn_kernel(const float* __restrict__ mask,
                 const float* __restrict__ tau,
                 const float* __restrict__ delta)
{
    const int bt  = blockIdx.z;
    const int h   = blockIdx.y;
    const int lq0 = blockIdx.x * 64;
    const int tid = threadIdx.x;
    const int ty  = tid >> 4;
    const int tx  = tid & 15;

    __shared__ float Qs[64][64];   // Q[l][e]
    __shared__ float KVs[64][64];  // K-phase: [k][s ^ (k&60)]; V-phase: [s][e]
    __shared__ float Ps[64][64];   // softmax probabilities

    const size_t head = (size_t)(bt * kH + h) * kL * kE;
    const float* Qp = g_Q + head;
    const float* Kp = g_K + head;
    const float* Vp = g_V + head;

    const float tauv   = __ldg(tau);
    const float deltav = __ldg(delta);
    const float sc     = 0.125f;   // 1/sqrt(64)

    // Load Q tile (64x64)
    #pragma unroll
    for (int i = 0; i < 4; i++) {
        int idx = tid + i * 256;
        int r = idx >> 4, q = idx & 15;
        *(float4*)&Qs[r][q * 4] = *(const float4*)(Qp + (size_t)(lq0 + r) * kE + q * 4);
    }

    float acc[4][4] = {};
    float mrow[4] = {-1e30f, -1e30f, -1e30f, -1e30f};
    float lrow[4] = {0.f, 0.f, 0.f, 0.f};

    for (int s0 = 0; s0 < kL; s0 += 64) {
        __syncthreads();  // prior-iter PV readers done before KVs overwrite; Qs visible (iter 0)

        // Load K tile transposed + swizzled: KVs[k][s ^ (k&60)] = K[s0+s][k]
        #pragma unroll
        for (int i = 0; i < 4; i++) {
            int idx = tid + i * 256;
            int s = idx >> 4, q = idx & 15;
            float4 v = *(const float4*)(Kp + (size_t)(s0 + s) * kE + q * 4);
            int k  = q * 4;
            int sw = k & 60;
            KVs[k + 0][s ^ sw] = v.x;
            KVs[k + 1][s ^ sw] = v.y;
            KVs[k + 2][s ^ sw] = v.z;
            KVs[k + 3][s ^ sw] = v.w;
        }
        __syncthreads();

        // S = Q K^T  (64x64 tile, 4x4 per thread)
        float sv[4][4] = {};
        #pragma unroll
        for (int k0 = 0; k0 < 64; k0 += 4) {
            float4 aF[4];
            #pragma unroll
            for (int ri = 0; ri < 4; ri++)
                aF[ri] = *(const float4*)&Qs[4 * ty + ri][k0];
            const int bc = (4 * tx) ^ k0;  // k0 multiple of 4 -> k0 & 60 == k0
            float4 bF[4];
            #pragma unroll
            for (int j = 0; j < 4; j++)
                bF[j] = *(const float4*)&KVs[k0 + j][bc];
            const float* ap = (const float*)aF;
            #pragma unroll
            for (int ri = 0; ri < 4; ri++) {
                #pragma unroll
                for (int j = 0; j < 4; j++) {
                    float avx = ap[ri * 4 + j];
                    sv[ri][0] += avx * bF[j].x;
                    sv[ri][1] += avx * bF[j].y;
                    sv[ri][2] += avx * bF[j].z;
                    sv[ri][3] += avx * bF[j].w;
                }
            }
        }

        // scale + mask + online softmax update
        const float* mbase = mask + (size_t)(lq0 + 4 * ty) * kL + s0 + 4 * tx;
        #pragma unroll
        for (int ri = 0; ri < 4; ri++) {
            float4 mv = __ldg((const float4*)(mbase + (size_t)ri * kL));
            float x0 = (sv[ri][0] * tauv + deltav) * sc * mv.x;
            float x1 = (sv[ri][1] * tauv + deltav) * sc * mv.y;
            float x2 = (sv[ri][2] * tauv + deltav) * sc * mv.z;
            float x3 = (sv[ri][3] * tauv + deltav) * sc * mv.w;

            float tm = fmaxf(fmaxf(x0, x1), fmaxf(x2, x3));
            tm = fmaxf(tm, __shfl_xor_sync(0xffffffffu, tm, 1));
            tm = fmaxf(tm, __shfl_xor_sync(0xffffffffu, tm, 2));
            tm = fmaxf(tm, __shfl_xor_sync(0xffffffffu, tm, 4));
            tm = fmaxf(tm, __shfl_xor_sync(0xffffffffu, tm, 8));

            float mnew = fmaxf(mrow[ri], tm);
            float corr = __expf(mrow[ri] - mnew);
            mrow[ri] = mnew;

            float p0 = __expf(x0 - mnew);
            float p1 = __expf(x1 - mnew);
            float p2 = __expf(x2 - mnew);
            float p3 = __expf(x3 - mnew);
            float rs = p0 + p1 + p2 + p3;
            rs += __shfl_xor_sync(0xffffffffu, rs, 1);
            rs += __shfl_xor_sync(0xffffffffu, rs, 2);
            rs += __shfl_xor_sync(0xffffffffu, rs, 4);
            rs += __shfl_xor_sync(0xffffffffu, rs, 8);

            lrow[ri] = lrow[ri] * corr + rs;
            acc[ri][0] *= corr;
            acc[ri][1] *= corr;
            acc[ri][2] *= corr;
            acc[ri][3] *= corr;

            Ps[4 * ty + ri][4 * tx + 0] = p0;
            Ps[4 * ty + ri][4 * tx + 1] = p1;
            Ps[4 * ty + ri][4 * tx + 2] = p2;
            Ps[4 * ty + ri][4 * tx + 3] = p3;
        }
        __syncthreads();  // Ps complete; all K reads done -> safe to overwrite KVs

        // Load V tile (plain layout [s][e])
        #pragma unroll
        for (int i = 0; i < 4; i++) {
            int idx = tid + i * 256;
            int s = idx >> 4, q = idx & 15;
            *(float4*)&KVs[s][q * 4] = *(const float4*)(Vp + (size_t)(s0 + s) * kE + q * 4);
        }
        __syncthreads();

        // acc += P @ V
        #pragma unroll
        for (int k0 = 0; k0 < 64; k0 += 4) {
            float4 aF[4];
            #pragma unroll
            for (int ri = 0; ri < 4; ri++)
                aF[ri] = *(const float4*)&Ps[4 * ty + ri][k0];
            float4 bF[4];
            #pragma unroll
            for (int j = 0; j < 4; j++)
                bF[j] = *(const float4*)&KVs[k0 + j][4 * tx];
            const float* ap = (const float*)aF;
            #pragma unroll
            for (int ri = 0; ri < 4; ri++) {
                #pragma unroll
                for (int j = 0; j < 4; j++) {
                    float avx = ap[ri * 4 + j];
                    acc[ri][0] += avx * bF[j].x;
                    acc[ri][1] += avx * bF[j].y;
                    acc[ri][2] += avx * bF[j].z;
                    acc[ri][3] += avx * bF[j].w;
                }
            }
        }
    }

    // Normalize and store attn output
    float* Op = g_A + head + (size_t)lq0 * kE;
    #pragma unroll
    for (int ri = 0; ri < 4; ri++) {
        float inv = 1.0f / lrow[ri];
        *(float4*)(Op + (size_t)(4 * ty + ri) * kE + 4 * tx) =
            make_float4(acc[ri][0] * inv, acc[ri][1] * inv,
                        acc[ri][2] * inv, acc[ri][3] * inv);
    }
}

// ---------------------------------------------------------------------------
// Kernel 3: out[bt,l,e] = sum_h w[h] * attn[bt,h,l,e]   (float4 vectorized)
// ---------------------------------------------------------------------------
__global__ __launch_bounds__(256)
void head_reduce(const float* __restrict__ w, float* __restrict__ out)
{
    const int total = kBT * kL * kE / 4;  // 262144 float4
    int v = blockIdx.x * 256 + threadIdx.x;
    if (v >= total) return;
    int bt = v >> 13;       // / (512*64/4)
    int r  = v & 8191;

    const float4* A4 = (const float4*)g_A;
    float4 s = make_float4(0.f, 0.f, 0.f, 0.f);
    #pragma unroll
    for (int h = 0; h < kH; h++) {
        float wh = __ldg(w + h);
        float4 a = A4[((size_t)bt * kH + h) * 8192 + r];
        s.x += wh * a.x;
        s.y += wh * a.y;
        s.z += wh * a.z;
        s.w += wh * a.w;
    }
    ((float4*)out)[v] = s;
}

// ---------------------------------------------------------------------------
extern "C" void kernel_launch(void* const* d_in, const int* in_sizes, int n_in,
                              void* d_out, int out_size)
{
    const float* q   = (const float*)d_in[0];
    const float* k   = (const float*)d_in[1];
    const float* v   = (const float*)d_in[2];
    const float* msk = (const float*)d_in[3];
    const float* Wq  = (const float*)d_in[4];
    const float* Wk  = (const float*)d_in[5];
    const float* Wv  = (const float*)d_in[6];
    const float* wh  = (const float*)d_in[7];
    const float* tau = (const float*)d_in[8];
    const float* del = (const float*)d_in[9];

    dim3 pg(kL / 64, kH, kBT);
    proj_kernel<<<pg, 256>>>(q, Wq, 0);
    proj_kernel<<<pg, 256>>>(k, Wk, 1);
    proj_kernel<<<pg, 256>>>(v, Wv, 2);

    attn_kernel<<<dim3(kL / 64, kH, kBT), 256>>>(msk, tau, del);

    head_reduce<<<(kBT * kL * kE / 4 + 255) / 256, 256>>>(wh, (float*)d_out);
}

// round 3
// speedup vs baseline: 1.3257x; 1.3257x over previous
#include <cuda_runtime.h>
#include <cstdint>

// Problem constants
namespace {
constexpr int kBT = 32;   // B*T
constexpr int kL  = 512;
constexpr int kD  = 512;
constexpr int kH  = 8;
constexpr int kE  = 64;

// tf32 mma.sync projection GEMM tiling
constexpr int CTA_M = 128;
constexpr int CTA_N = 128;
constexpr int BK    = 32;
constexpr int LDSS  = 136;                 // smem row stride (mod 32 == 8 -> conflict-free)
constexpr int TILE_FLOATS = BK * LDSS;     // 4352 floats per operand buffer
constexpr uint32_t SMEM_BYTES = 4 * TILE_FLOATS * 4;  // A0,B0,A1,B1 = 69632 B
}

// Scratch (device globals: allocation-free per harness rules).
__device__ __align__(16) float g_Q[kBT * kH * kL * kE];
__device__ __align__(16) float g_K[kBT * kH * kL * kE];
__device__ __align__(16) float g_V[kBT * kH * kL * kE];
__device__ __align__(16) float g_A[kBT * kH * kL * kE];
__device__ __align__(16) float g_Wt[3 * kD * kH * kE];   // transposed weights [w][n][k]

__device__ __forceinline__ uint32_t f2tf32(float x) {
    uint32_t r;
    asm("cvt.rna.tf32.f32 %0, %1;" : "=r"(r) : "f"(x));
    return r;
}

__device__ __forceinline__ void mma_tf32(float* c, const uint32_t* a, const uint32_t* b) {
    asm volatile(
        "mma.sync.aligned.m16n8k8.row.col.f32.tf32.tf32.f32 "
        "{%0,%1,%2,%3}, {%4,%5,%6,%7}, {%8,%9}, {%0,%1,%2,%3};"
        : "+f"(c[0]), "+f"(c[1]), "+f"(c[2]), "+f"(c[3])
        : "r"(a[0]), "r"(a[1]), "r"(a[2]), "r"(a[3]), "r"(b[0]), "r"(b[1]));
}

// ---------------------------------------------------------------------------
// Kernel 0: weight transpose  Wt[w][n][k] = W_w[k][n]   (512x512 each)
// ---------------------------------------------------------------------------
__global__ __launch_bounds__(256)
void transpose_w(const float* __restrict__ Wq, const float* __restrict__ Wk,
                 const float* __restrict__ Wv)
{
    __shared__ float t[32][33];
    const int w = blockIdx.z;
    const float* W = (w == 0) ? Wq : (w == 1) ? Wk : Wv;
    float* Wt = g_Wt + (size_t)w * (kD * kH * kE);
    const int x0 = blockIdx.x * 32, y0 = blockIdx.y * 32;
    const int tx = threadIdx.x, ty = threadIdx.y;
    #pragma unroll
    for (int i = 0; i < 32; i += 8)
        t[ty + i][tx] = W[(size_t)(y0 + ty + i) * 512 + x0 + tx];
    __syncthreads();
    #pragma unroll
    for (int i = 0; i < 32; i += 8)
        Wt[(size_t)(x0 + ty + i) * 512 + y0 + tx] = t[tx][ty + i];
}

// ---------------------------------------------------------------------------
// Kernel 1: tf32 mma.sync projection GEMM.
// Per (bt, w): C[l, n] = X[l, d] * W[d, n], n = h*64+e, B = W^T stored [n][k].
// CTA 128x128, BK=32, 8 warps each 64x32 (4x4 m16n8k8 tiles).
// Smem K-major with stride 136 (bank-conflict-free fragment gathers).
// Output head-major: out[((bt*H+h)*L + l)*E + e].
// ---------------------------------------------------------------------------
__global__ __launch_bounds__(256)
void proj_mma(const float* __restrict__ Xq, const float* __restrict__ Xk,
              const float* __restrict__ Xv)
{
    extern __shared__ float S[];
    float* Abuf[2] = { S,                  S + 2 * TILE_FLOATS };
    float* Bbuf[2] = { S + TILE_FLOATS,    S + 3 * TILE_FLOATS };

    const int tid = threadIdx.x;
    const int wid = tid >> 5;
    const int lane = tid & 31;
    const int gid = lane >> 2;     // group id (0..7)
    const int tig = lane & 3;      // thread in group

    const int w  = blockIdx.z;
    const int bt = blockIdx.y;
    const int m0 = (blockIdx.x >> 2) * CTA_M;
    const int n0 = (blockIdx.x & 3) * CTA_N;
    const int wm = (wid >> 2) * 64;   // warp m offset within CTA
    const int wn = (wid & 3) * 32;    // warp n offset within CTA

    const float* X  = (w == 0) ? Xq : (w == 1) ? Xk : Xv;
    const float* Wt = g_Wt + (size_t)w * (kD * kH * kE);
    float* out      = (w == 0) ? g_Q : (w == 1) ? g_K : g_V;

    const float* Ag = X + ((size_t)bt * kL + m0) * kD;   // [r][k]
    const float* Bg = Wt + (size_t)n0 * kD;              // [n][k]

    // Per-thread gmem tile mapping: 4 float4 per operand per tile
    int rr[4], ff[4];
    #pragma unroll
    for (int i = 0; i < 4; i++) {
        int idx = tid + i * 256;
        rr[i] = idx & 127;
        ff[i] = idx >> 7;     // 0..7 -> k chunk of 4
    }

    float4 ra[4], rb[4];
    // Prologue: tile 0
    #pragma unroll
    for (int i = 0; i < 4; i++) {
        ra[i] = *(const float4*)(Ag + (size_t)rr[i] * kD + ff[i] * 4);
        rb[i] = *(const float4*)(Bg + (size_t)rr[i] * kD + ff[i] * 4);
    }
    #pragma unroll
    for (int i = 0; i < 4; i++) {
        int kb = ff[i] * 4;
        float* Ad = Abuf[0];
        float* Bd = Bbuf[0];
        const float* av = (const float*)&ra[i];
        const float* bv = (const float*)&rb[i];
        #pragma unroll
        for (int j = 0; j < 4; j++) {
            Ad[(kb + j) * LDSS + rr[i]] = __uint_as_float(f2tf32(av[j]));
            Bd[(kb + j) * LDSS + rr[i]] = __uint_as_float(f2tf32(bv[j]));
        }
    }
    __syncthreads();

    float acc[4][4][4] = {};

    const int NT = kD / BK;   // 16
    for (int t = 0; t < NT; t++) {
        // Prefetch next tile into registers
        if (t + 1 < NT) {
            const float* Agn = Ag + (t + 1) * BK;
            const float* Bgn = Bg + (t + 1) * BK;
            #pragma unroll
            for (int i = 0; i < 4; i++) {
                ra[i] = *(const float4*)(Agn + (size_t)rr[i] * kD + ff[i] * 4);
                rb[i] = *(const float4*)(Bgn + (size_t)rr[i] * kD + ff[i] * 4);
            }
        }

        // Compute on current buffer
        const float* As = Abuf[t & 1];
        const float* Bs = Bbuf[t & 1];
        #pragma unroll
        for (int ks = 0; ks < 4; ks++) {
            const int kr = ks * 8 + tig;
            uint32_t afr[4][4], bfr[4][2];
            #pragma unroll
            for (int mt = 0; mt < 4; mt++) {
                const int m = wm + mt * 16 + gid;
                afr[mt][0] = __float_as_uint(As[kr * LDSS + m]);
                afr[mt][1] = __float_as_uint(As[kr * LDSS + m + 8]);
                afr[mt][2] = __float_as_uint(As[(kr + 4) * LDSS + m]);
                afr[mt][3] = __float_as_uint(As[(kr + 4) * LDSS + m + 8]);
            }
            #pragma unroll
            for (int nt = 0; nt < 4; nt++) {
                const int n = wn + nt * 8 + gid;
                bfr[nt][0] = __float_as_uint(Bs[kr * LDSS + n]);
                bfr[nt][1] = __float_as_uint(Bs[(kr + 4) * LDSS + n]);
            }
            #pragma unroll
            for (int mt = 0; mt < 4; mt++)
                #pragma unroll
                for (int nt = 0; nt < 4; nt++)
                    mma_tf32(acc[mt][nt], afr[mt], bfr[nt]);
        }

        // Stage next tile into the other buffer
        if (t + 1 < NT) {
            __syncthreads();
            float* Ad = Abuf[(t + 1) & 1];
            float* Bd = Bbuf[(t + 1) & 1];
            #pragma unroll
            for (int i = 0; i < 4; i++) {
                int kb = ff[i] * 4;
                const float* av = (const float*)&ra[i];
                const float* bv = (const float*)&rb[i];
                #pragma unroll
                for (int j = 0; j < 4; j++) {
                    Ad[(kb + j) * LDSS + rr[i]] = __uint_as_float(f2tf32(av[j]));
                    Bd[(kb + j) * LDSS + rr[i]] = __uint_as_float(f2tf32(bv[j]));
                }
            }
            __syncthreads();
        }
    }

    // Epilogue: head-major store, float2 per (c0,c1) / (c2,c3)
    #pragma unroll
    for (int mt = 0; mt < 4; mt++) {
        #pragma unroll
        for (int nt = 0; nt < 4; nt++) {
            const int n = n0 + wn + nt * 8 + tig * 2;
            const int h = n >> 6;
            const int e = n & 63;
            const int l = m0 + wm + mt * 16 + gid;
            float* O = out + (((size_t)(bt * kH + h) * kL) + l) * kE + e;
            *(float2*)O = make_float2(acc[mt][nt][0], acc[mt][nt][1]);
            *(float2*)(O + 8 * (size_t)kE) = make_float2(acc[mt][nt][2], acc[mt][nt][3]);
        }
    }
}

// ---------------------------------------------------------------------------
// Kernel 2: fused attention per (bt, h), 64 query rows per CTA, flash-style
// online softmax over 8 key tiles of 64. (unchanged from round 1 — passing)
// ---------------------------------------------------------------------------
__global__ __launch_bounds__(256)
void attn_kernel(const float* __restrict__ mask,
                 const float* __restrict__ tau,
                 const float* __restrict__ delta)
{
    const int bt  = blockIdx.z;
    const int h   = blockIdx.y;
    const int lq0 = blockIdx.x * 64;
    const int tid = threadIdx.x;
    const int ty  = tid >> 4;
    const int tx  = tid & 15;

    __shared__ float Qs[64][64];
    __shared__ float KVs[64][64];
    __shared__ float Ps[64][64];

    const size_t head = (size_t)(bt * kH + h) * kL * kE;
    const float* Qp = g_Q + head;
    const float* Kp = g_K + head;
    const float* Vp = g_V + head;

    const float tauv   = __ldg(tau);
    const float deltav = __ldg(delta);
    const float sc     = 0.125f;

    #pragma unroll
    for (int i = 0; i < 4; i++) {
        int idx = tid + i * 256;
        int r = idx >> 4, q = idx & 15;
        *(float4*)&Qs[r][q * 4] = *(const float4*)(Qp + (size_t)(lq0 + r) * kE + q * 4);
    }

    float acc[4][4] = {};
    float mrow[4] = {-1e30f, -1e30f, -1e30f, -1e30f};
    float lrow[4] = {0.f, 0.f, 0.f, 0.f};

    for (int s0 = 0; s0 < kL; s0 += 64) {
        __syncthreads();

        #pragma unroll
        for (int i = 0; i < 4; i++) {
            int idx = tid + i * 256;
            int s = idx >> 4, q = idx & 15;
            float4 v = *(const float4*)(Kp + (size_t)(s0 + s) * kE + q * 4);
            int k  = q * 4;
            int sw = k & 60;
            KVs[k + 0][s ^ sw] = v.x;
            KVs[k + 1][s ^ sw] = v.y;
            KVs[k + 2][s ^ sw] = v.z;
            KVs[k + 3][s ^ sw] = v.w;
        }
        __syncthreads();

        float sv[4][4] = {};
        #pragma unroll
        for (int k0 = 0; k0 < 64; k0 += 4) {
            float4 aF[4];
            #pragma unroll
            for (int ri = 0; ri < 4; ri++)
                aF[ri] = *(const float4*)&Qs[4 * ty + ri][k0];
            const int bc = (4 * tx) ^ k0;
            float4 bF[4];
            #pragma unroll
            for (int j = 0; j < 4; j++)
                bF[j] = *(const float4*)&KVs[k0 + j][bc];
            const float* ap = (const float*)aF;
            #pragma unroll
            for (int ri = 0; ri < 4; ri++) {
                #pragma unroll
                for (int j = 0; j < 4; j++) {
                    float avx = ap[ri * 4 + j];
                    sv[ri][0] += avx * bF[j].x;
                    sv[ri][1] += avx * bF[j].y;
                    sv[ri][2] += avx * bF[j].z;
                    sv[ri][3] += avx * bF[j].w;
                }
            }
        }

        const float* mbase = mask + (size_t)(lq0 + 4 * ty) * kL + s0 + 4 * tx;
        #pragma unroll
        for (int ri = 0; ri < 4; ri++) {
            float4 mv = __ldg((const float4*)(mbase + (size_t)ri * kL));
            float x0 = (sv[ri][0] * tauv + deltav) * sc * mv.x;
            float x1 = (sv[ri][1] * tauv + deltav) * sc * mv.y;
            float x2 = (sv[ri][2] * tauv + deltav) * sc * mv.z;
            float x3 = (sv[ri][3] * tauv + deltav) * sc * mv.w;

            float tm = fmaxf(fmaxf(x0, x1), fmaxf(x2, x3));
            tm = fmaxf(tm, __shfl_xor_sync(0xffffffffu, tm, 1));
            tm = fmaxf(tm, __shfl_xor_sync(0xffffffffu, tm, 2));
            tm = fmaxf(tm, __shfl_xor_sync(0xffffffffu, tm, 4));
            tm = fmaxf(tm, __shfl_xor_sync(0xffffffffu, tm, 8));

            float mnew = fmaxf(mrow[ri], tm);
            float corr = __expf(mrow[ri] - mnew);
            mrow[ri] = mnew;

            float p0 = __expf(x0 - mnew);
            float p1 = __expf(x1 - mnew);
            float p2 = __expf(x2 - mnew);
            float p3 = __expf(x3 - mnew);
            float rs = p0 + p1 + p2 + p3;
            rs += __shfl_xor_sync(0xffffffffu, rs, 1);
            rs += __shfl_xor_sync(0xffffffffu, rs, 2);
            rs += __shfl_xor_sync(0xffffffffu, rs, 4);
            rs += __shfl_xor_sync(0xffffffffu, rs, 8);

            lrow[ri] = lrow[ri] * corr + rs;
            acc[ri][0] *= corr;
            acc[ri][1] *= corr;
            acc[ri][2] *= corr;
            acc[ri][3] *= corr;

            Ps[4 * ty + ri][4 * tx + 0] = p0;
            Ps[4 * ty + ri][4 * tx + 1] = p1;
            Ps[4 * ty + ri][4 * tx + 2] = p2;
            Ps[4 * ty + ri][4 * tx + 3] = p3;
        }
        __syncthreads();

        #pragma unroll
        for (int i = 0; i < 4; i++) {
            int idx = tid + i * 256;
            int s = idx >> 4, q = idx & 15;
            *(float4*)&KVs[s][q * 4] = *(const float4*)(Vp + (size_t)(s0 + s) * kE + q * 4);
        }
        __syncthreads();

        #pragma unroll
        for (int k0 = 0; k0 < 64; k0 += 4) {
            float4 aF[4];
            #pragma unroll
            for (int ri = 0; ri < 4; ri++)
                aF[ri] = *(const float4*)&Ps[4 * ty + ri][k0];
            float4 bF[4];
            #pragma unroll
            for (int j = 0; j < 4; j++)
                bF[j] = *(const float4*)&KVs[k0 + j][4 * tx];
            const float* ap = (const float*)aF;
            #pragma unroll
            for (int ri = 0; ri < 4; ri++) {
                #pragma unroll
                for (int j = 0; j < 4; j++) {
                    float avx = ap[ri * 4 + j];
                    acc[ri][0] += avx * bF[j].x;
                    acc[ri][1] += avx * bF[j].y;
                    acc[ri][2] += avx * bF[j].z;
                    acc[ri][3] += avx * bF[j].w;
                }
            }
        }
    }

    float* Op = g_A + head + (size_t)lq0 * kE;
    #pragma unroll
    for (int ri = 0; ri < 4; ri++) {
        float inv = 1.0f / lrow[ri];
        *(float4*)(Op + (size_t)(4 * ty + ri) * kE + 4 * tx) =
            make_float4(acc[ri][0] * inv, acc[ri][1] * inv,
                        acc[ri][2] * inv, acc[ri][3] * inv);
    }
}

// ---------------------------------------------------------------------------
// Kernel 3: out[bt,l,e] = sum_h w[h] * attn[bt,h,l,e]
// ---------------------------------------------------------------------------
__global__ __launch_bounds__(256)
void head_reduce(const float* __restrict__ w, float* __restrict__ out)
{
    const int total = kBT * kL * kE / 4;
    int v = blockIdx.x * 256 + threadIdx.x;
    if (v >= total) return;
    int bt = v >> 13;
    int r  = v & 8191;

    const float4* A4 = (const float4*)g_A;
    float4 s = make_float4(0.f, 0.f, 0.f, 0.f);
    #pragma unroll
    for (int h = 0; h < kH; h++) {
        float wh = __ldg(w + h);
        float4 a = A4[((size_t)bt * kH + h) * 8192 + r];
        s.x += wh * a.x;
        s.y += wh * a.y;
        s.z += wh * a.z;
        s.w += wh * a.w;
    }
    ((float4*)out)[v] = s;
}

// ---------------------------------------------------------------------------
extern "C" void kernel_launch(void* const* d_in, const int* in_sizes, int n_in,
                              void* d_out, int out_size)
{
    const float* q   = (const float*)d_in[0];
    const float* k   = (const float*)d_in[1];
    const float* v   = (const float*)d_in[2];
    const float* msk = (const float*)d_in[3];
    const float* Wq  = (const float*)d_in[4];
    const float* Wk  = (const float*)d_in[5];
    const float* Wv  = (const float*)d_in[6];
    const float* wh  = (const float*)d_in[7];
    const float* tau = (const float*)d_in[8];
    const float* del = (const float*)d_in[9];

    static bool attr_set = false;
    if (!attr_set) {
        cudaFuncSetAttribute(proj_mma, cudaFuncAttributeMaxDynamicSharedMemorySize,
                             (int)SMEM_BYTES);
        attr_set = true;
    }

    transpose_w<<<dim3(16, 16, 3), dim3(32, 8)>>>(Wq, Wk, Wv);
    proj_mma<<<dim3(16, kBT, 3), 256, SMEM_BYTES>>>(q, k, v);
    attn_kernel<<<dim3(kL / 64, kH, kBT), 256>>>(msk, tau, del);
    head_reduce<<<(kBT * kL * kE / 4 + 255) / 256, 256>>>(wh, (float*)d_out);
}

// round 5
// speedup vs baseline: 1.5548x; 1.1728x over previous
#include <cuda_runtime.h>
#include <cstdint>

// Problem constants
namespace {
constexpr int kBT = 32;   // B*T
constexpr int kL  = 512;
constexpr int kD  = 512;
constexpr int kH  = 8;
constexpr int kE  = 64;

// tf32 mma.sync projection GEMM tiling
constexpr int CTA_M = 128;
constexpr int CTA_N = 128;
constexpr int BK    = 32;
constexpr int LDSS  = 136;                 // smem row stride (mod 32 == 8 -> conflict-free)
constexpr int TILE_FLOATS = BK * LDSS;
constexpr uint32_t SMEM_BYTES = 4 * TILE_FLOATS * 4;  // 69632 B

// attention mma tiling
constexpr int QS_STR = 68;   // [m][k] stride: 68 % 32 == 4 -> frag reads conflict-free
constexpr int KS_STR = 68;   // [s][e]
constexpr int VS_STR = 72;   // [s][e]: 72 % 32 == 8 -> frag reads conflict-free
constexpr int SM_QS = 0;                       // 128 x 68 (reused as Ps)
constexpr int SM_KS = 128 * QS_STR;            // 64 x 68
constexpr int SM_VS = SM_KS + 64 * KS_STR;     // 64 x 72
constexpr uint32_t ATTN_SMEM = (uint32_t)(SM_VS + 64 * VS_STR) * 4;  // 70656 B
}

// Scratch (device globals: allocation-free per harness rules).
__device__ __align__(16) float g_Q[kBT * kH * kL * kE];
__device__ __align__(16) float g_K[kBT * kH * kL * kE];
__device__ __align__(16) float g_V[kBT * kH * kL * kE];
__device__ __align__(16) float g_A[kBT * kH * kL * kE];
__device__ __align__(16) float g_Wt[3 * kD * kH * kE];   // transposed weights [w][n][k]
__device__ int g_maskones;

__device__ __forceinline__ uint32_t f2tf32(float x) {
    uint32_t r;
    asm("cvt.rna.tf32.f32 %0, %1;" : "=r"(r) : "f"(x));
    return r;
}

__device__ __forceinline__ void mma_tf32(float* c, const uint32_t* a, const uint32_t* b) {
    asm volatile(
        "mma.sync.aligned.m16n8k8.row.col.f32.tf32.tf32.f32 "
        "{%0,%1,%2,%3}, {%4,%5,%6,%7}, {%8,%9}, {%0,%1,%2,%3};"
        : "+f"(c[0]), "+f"(c[1]), "+f"(c[2]), "+f"(c[3])
        : "r"(a[0]), "r"(a[1]), "r"(a[2]), "r"(a[3]), "r"(b[0]), "r"(b[1]));
}

// Split fp32 x into hi (tf32-exact, mantissa-truncated) + lo (tf32-rounded residual).
__device__ __forceinline__ void tf32_split(float x, uint32_t& hi, uint32_t& lo) {
    hi = __float_as_uint(x) & 0xffffe000u;
    lo = f2tf32(x - __uint_as_float(hi));
}

// ---------------------------------------------------------------------------
// Kernel 0: weight transpose  Wt[w][n][k] = W_w[k][n]   (512x512 each)
// ---------------------------------------------------------------------------
__global__ __launch_bounds__(256)
void transpose_w(const float* __restrict__ Wq, const float* __restrict__ Wk,
                 const float* __restrict__ Wv)
{
    __shared__ float t[32][33];
    const int w = blockIdx.z;
    const float* W = (w == 0) ? Wq : (w == 1) ? Wk : Wv;
    float* Wt = g_Wt + (size_t)w * (kD * kH * kE);
    const int x0 = blockIdx.x * 32, y0 = blockIdx.y * 32;
    const int tx = threadIdx.x, ty = threadIdx.y;
    #pragma unroll
    for (int i = 0; i < 32; i += 8)
        t[ty + i][tx] = W[(size_t)(y0 + ty + i) * 512 + x0 + tx];
    __syncthreads();
    #pragma unroll
    for (int i = 0; i < 32; i += 8)
        Wt[(size_t)(x0 + ty + i) * 512 + y0 + tx] = t[tx][ty + i];
}

// ---------------------------------------------------------------------------
// Mask all-ones detection (deterministic; enables fast path in attn_mma)
// ---------------------------------------------------------------------------
__global__ void mask_init() { g_maskones = 1; }
__global__ __launch_bounds__(256)
void mask_check(const float* __restrict__ mask)
{
    int i = blockIdx.x * 256 + threadIdx.x;
    if (i < kL * kL && __ldg(mask + i) != 1.0f) g_maskones = 0;
}

// ---------------------------------------------------------------------------
// Kernel 1: tf32 mma.sync projection GEMM (unchanged from round 3 — passing).
// ---------------------------------------------------------------------------
__global__ __launch_bounds__(256)
void proj_mma(const float* __restrict__ Xq, const float* __restrict__ Xk,
              const float* __restrict__ Xv)
{
    extern __shared__ float S[];
    float* Abuf[2] = { S,                  S + 2 * TILE_FLOATS };
    float* Bbuf[2] = { S + TILE_FLOATS,    S + 3 * TILE_FLOATS };

    const int tid = threadIdx.x;
    const int wid = tid >> 5;
    const int lane = tid & 31;
    const int gid = lane >> 2;
    const int tig = lane & 3;

    const int w  = blockIdx.z;
    const int bt = blockIdx.y;
    const int m0 = (blockIdx.x >> 2) * CTA_M;
    const int n0 = (blockIdx.x & 3) * CTA_N;
    const int wm = (wid >> 2) * 64;
    const int wn = (wid & 3) * 32;

    const float* X  = (w == 0) ? Xq : (w == 1) ? Xk : Xv;
    const float* Wt = g_Wt + (size_t)w * (kD * kH * kE);
    float* out      = (w == 0) ? g_Q : (w == 1) ? g_K : g_V;

    const float* Ag = X + ((size_t)bt * kL + m0) * kD;
    const float* Bg = Wt + (size_t)n0 * kD;

    int rr[4], ff[4];
    #pragma unroll
    for (int i = 0; i < 4; i++) {
        int idx = tid + i * 256;
        rr[i] = idx & 127;
        ff[i] = idx >> 7;
    }

    float4 ra[4], rb[4];
    #pragma unroll
    for (int i = 0; i < 4; i++) {
        ra[i] = *(const float4*)(Ag + (size_t)rr[i] * kD + ff[i] * 4);
        rb[i] = *(const float4*)(Bg + (size_t)rr[i] * kD + ff[i] * 4);
    }
    #pragma unroll
    for (int i = 0; i < 4; i++) {
        int kb = ff[i] * 4;
        float* Ad = Abuf[0];
        float* Bd = Bbuf[0];
        const float* av = (const float*)&ra[i];
        const float* bv = (const float*)&rb[i];
        #pragma unroll
        for (int j = 0; j < 4; j++) {
            Ad[(kb + j) * LDSS + rr[i]] = __uint_as_float(f2tf32(av[j]));
            Bd[(kb + j) * LDSS + rr[i]] = __uint_as_float(f2tf32(bv[j]));
        }
    }
    __syncthreads();

    float acc[4][4][4] = {};

    const int NT = kD / BK;
    for (int t = 0; t < NT; t++) {
        if (t + 1 < NT) {
            const float* Agn = Ag + (t + 1) * BK;
            const float* Bgn = Bg + (t + 1) * BK;
            #pragma unroll
            for (int i = 0; i < 4; i++) {
                ra[i] = *(const float4*)(Agn + (size_t)rr[i] * kD + ff[i] * 4);
                rb[i] = *(const float4*)(Bgn + (size_t)rr[i] * kD + ff[i] * 4);
            }
        }

        const float* As = Abuf[t & 1];
        const float* Bs = Bbuf[t & 1];
        #pragma unroll
        for (int ks = 0; ks < 4; ks++) {
            const int kr = ks * 8 + tig;
            uint32_t afr[4][4], bfr[4][2];
            #pragma unroll
            for (int mt = 0; mt < 4; mt++) {
                const int m = wm + mt * 16 + gid;
                afr[mt][0] = __float_as_uint(As[kr * LDSS + m]);
                afr[mt][1] = __float_as_uint(As[kr * LDSS + m + 8]);
                afr[mt][2] = __float_as_uint(As[(kr + 4) * LDSS + m]);
                afr[mt][3] = __float_as_uint(As[(kr + 4) * LDSS + m + 8]);
            }
            #pragma unroll
            for (int nt = 0; nt < 4; nt++) {
                const int n = wn + nt * 8 + gid;
                bfr[nt][0] = __float_as_uint(Bs[kr * LDSS + n]);
                bfr[nt][1] = __float_as_uint(Bs[(kr + 4) * LDSS + n]);
            }
            #pragma unroll
            for (int mt = 0; mt < 4; mt++)
                #pragma unroll
                for (int nt = 0; nt < 4; nt++)
                    mma_tf32(acc[mt][nt], afr[mt], bfr[nt]);
        }

        if (t + 1 < NT) {
            __syncthreads();
            float* Ad = Abuf[(t + 1) & 1];
            float* Bd = Bbuf[(t + 1) & 1];
            #pragma unroll
            for (int i = 0; i < 4; i++) {
                int kb = ff[i] * 4;
                const float* av = (const float*)&ra[i];
                const float* bv = (const float*)&rb[i];
                #pragma unroll
                for (int j = 0; j < 4; j++) {
                    Ad[(kb + j) * LDSS + rr[i]] = __uint_as_float(f2tf32(av[j]));
                    Bd[(kb + j) * LDSS + rr[i]] = __uint_as_float(f2tf32(bv[j]));
                }
            }
            __syncthreads();
        }
    }

    #pragma unroll
    for (int mt = 0; mt < 4; mt++) {
        #pragma unroll
        for (int nt = 0; nt < 4; nt++) {
            const int n = n0 + wn + nt * 8 + tig * 2;
            const int h = n >> 6;
            const int e = n & 63;
            const int l = m0 + wm + mt * 16 + gid;
            float* O = out + (((size_t)(bt * kH + h) * kL) + l) * kE + e;
            *(float2*)O = make_float2(acc[mt][nt][0], acc[mt][nt][1]);
            *(float2*)(O + 8 * (size_t)kE) = make_float2(acc[mt][nt][2], acc[mt][nt][3]);
        }
    }
}

// ---------------------------------------------------------------------------
// Kernel 2: flash attention with tf32x3 mma.sync (fp32-equivalent accuracy).
// CTA = 128 q-rows, 8 warps x 16 rows, s-tiles of 64.
// Qs[m][k]@68 (reused as Ps), Ks[s][e]@68, Vs[s][e]@72 -> all fragment
// gathers bank-conflict-free, no smem transposes.
// ---------------------------------------------------------------------------
__global__ __launch_bounds__(256, 2)
void attn_mma(const float* __restrict__ mask,
              const float* __restrict__ tau,
              const float* __restrict__ delta)
{
    extern __shared__ float sm[];
    float* Qs = sm + SM_QS;   // [128][68], becomes Ps after Q frags are read
    float* Ks = sm + SM_KS;   // [64][68]
    float* Vs = sm + SM_VS;   // [64][72]

    const int tid  = threadIdx.x;
    const int wid  = tid >> 5;
    const int lane = tid & 31;
    const int gid  = lane >> 2;
    const int tig  = lane & 3;

    const int bt = blockIdx.z, h = blockIdx.y;
    const int m0 = blockIdx.x * 128;
    const int wm = wid * 16;

    const size_t head = (size_t)(bt * kH + h) * (kL * kE);
    const float* Qp = g_Q + head + (size_t)m0 * kE;
    const float* Kp = g_K + head;
    const float* Vp = g_V + head;

    const float sc = 0.125f;
    const float ta = __ldg(tau) * sc;
    const float db = __ldg(delta) * sc;
    const int ones = g_maskones;

    // Load Q tile [128][64] -> Qs[m][k]
    #pragma unroll
    for (int i = 0; i < 8; i++) {
        int idx = tid + i * 256;
        int m = idx >> 4, c = (idx & 15) * 4;
        *(float4*)(Qs + m * QS_STR + c) = *(const float4*)(Qp + m * kE + c);
    }
    __syncthreads();

    // Q fragments (raw fp32, split per-use)
    float qf[8][4];
    #pragma unroll
    for (int ks = 0; ks < 8; ks++) {
        const float* qb = Qs + (wm + gid) * QS_STR + ks * 8 + tig;
        qf[ks][0] = qb[0];
        qf[ks][1] = qb[8 * QS_STR];
        qf[ks][2] = qb[4];
        qf[ks][3] = qb[8 * QS_STR + 4];
    }

    float oacc[8][4] = {};
    float m0r = -1e30f, m1r = -1e30f, l0r = 0.f, l1r = 0.f;

    for (int s0 = 0; s0 < kL; s0 += 64) {
        if (s0) __syncthreads();   // prev tile's PV readers done with Ps/Vs/Ks

        // Load K,V tiles [64][64]  (FIXED: full 64 columns, 4 x 256 float4 each)
        #pragma unroll
        for (int i = 0; i < 4; i++) {
            int idx = tid + i * 256;
            int s = idx >> 4, c = (idx & 15) * 4;
            *(float4*)(Ks + s * KS_STR + c) = *(const float4*)(Kp + (s0 + s) * kE + c);
            *(float4*)(Vs + s * VS_STR + c) = *(const float4*)(Vp + (s0 + s) * kE + c);
        }
        __syncthreads();

        // ---- S = Q K^T, 3-term tf32 ----
        float sacc[8][4] = {};
        #pragma unroll
        for (int ks = 0; ks < 8; ks++) {
            uint32_t qhi[4], qlo[4];
            #pragma unroll
            for (int j = 0; j < 4; j++) tf32_split(qf[ks][j], qhi[j], qlo[j]);
            #pragma unroll
            for (int nt = 0; nt < 8; nt++) {
                const float* kb = Ks + (nt * 8 + gid) * KS_STR + ks * 8 + tig;
                float k0 = kb[0], k1 = kb[4];
                uint32_t kh[2], kl[2];
                tf32_split(k0, kh[0], kl[0]);
                tf32_split(k1, kh[1], kl[1]);
                mma_tf32(sacc[nt], qhi, kh);
                mma_tf32(sacc[nt], qhi, kl);
                mma_tf32(sacc[nt], qlo, kh);
            }
        }

        // ---- scale (+mask) + online softmax ----
        if (ones) {
            #pragma unroll
            for (int nt = 0; nt < 8; nt++)
                #pragma unroll
                for (int j = 0; j < 4; j++)
                    sacc[nt][j] = fmaf(sacc[nt][j], ta, db);
        } else {
            const float* mr0 = mask + (size_t)(m0 + wm + gid) * kL + s0;
            const float* mr1 = mr0 + 8 * (size_t)kL;
            #pragma unroll
            for (int nt = 0; nt < 8; nt++) {
                float2 mv0 = __ldg((const float2*)(mr0 + nt * 8 + tig * 2));
                float2 mv1 = __ldg((const float2*)(mr1 + nt * 8 + tig * 2));
                sacc[nt][0] = fmaf(sacc[nt][0], ta, db) * mv0.x;
                sacc[nt][1] = fmaf(sacc[nt][1], ta, db) * mv0.y;
                sacc[nt][2] = fmaf(sacc[nt][2], ta, db) * mv1.x;
                sacc[nt][3] = fmaf(sacc[nt][3], ta, db) * mv1.y;
            }
        }

        float tm0 = -1e30f, tm1 = -1e30f;
        #pragma unroll
        for (int nt = 0; nt < 8; nt++) {
            tm0 = fmaxf(tm0, fmaxf(sacc[nt][0], sacc[nt][1]));
            tm1 = fmaxf(tm1, fmaxf(sacc[nt][2], sacc[nt][3]));
        }
        tm0 = fmaxf(tm0, __shfl_xor_sync(0xffffffffu, tm0, 1));
        tm0 = fmaxf(tm0, __shfl_xor_sync(0xffffffffu, tm0, 2));
        tm1 = fmaxf(tm1, __shfl_xor_sync(0xffffffffu, tm1, 1));
        tm1 = fmaxf(tm1, __shfl_xor_sync(0xffffffffu, tm1, 2));

        float mn0 = fmaxf(m0r, tm0), mn1 = fmaxf(m1r, tm1);
        float c0 = __expf(m0r - mn0), c1 = __expf(m1r - mn1);
        m0r = mn0; m1r = mn1;

        float rs0 = 0.f, rs1 = 0.f;
        float* pb0 = Qs + (wm + gid) * QS_STR + tig * 2;
        float* pb1 = pb0 + 8 * QS_STR;
        #pragma unroll
        for (int nt = 0; nt < 8; nt++) {
            float p0 = __expf(sacc[nt][0] - mn0);
            float p1 = __expf(sacc[nt][1] - mn0);
            float p2 = __expf(sacc[nt][2] - mn1);
            float p3 = __expf(sacc[nt][3] - mn1);
            rs0 += p0 + p1;
            rs1 += p2 + p3;
            pb0[nt * 8 + 0] = p0;
            pb0[nt * 8 + 1] = p1;
            pb1[nt * 8 + 0] = p2;
            pb1[nt * 8 + 1] = p3;
            oacc[nt][0] *= c0; oacc[nt][1] *= c0;
            oacc[nt][2] *= c1; oacc[nt][3] *= c1;
        }
        rs0 += __shfl_xor_sync(0xffffffffu, rs0, 1);
        rs0 += __shfl_xor_sync(0xffffffffu, rs0, 2);
        rs1 += __shfl_xor_sync(0xffffffffu, rs1, 1);
        rs1 += __shfl_xor_sync(0xffffffffu, rs1, 2);
        l0r = l0r * c0 + rs0;
        l1r = l1r * c1 + rs1;

        __syncwarp();   // P rows of this warp complete (cross-lane smem visibility)

        // ---- O += P V, 3-term tf32 ----
        #pragma unroll
        for (int ks = 0; ks < 8; ks++) {
            const float* pf = Qs + (wm + gid) * QS_STR + ks * 8 + tig;
            float p0 = pf[0], p1 = pf[8 * QS_STR], p2 = pf[4], p3 = pf[8 * QS_STR + 4];
            uint32_t phi[4], plo[4];
            tf32_split(p0, phi[0], plo[0]);
            tf32_split(p1, phi[1], plo[1]);
            tf32_split(p2, phi[2], plo[2]);
            tf32_split(p3, phi[3], plo[3]);
            #pragma unroll
            for (int nt = 0; nt < 8; nt++) {
                const float* vb = Vs + (ks * 8 + tig) * VS_STR + nt * 8 + gid;
                float v0 = vb[0], v1 = vb[4 * VS_STR];
                uint32_t vh[2], vl[2];
                tf32_split(v0, vh[0], vl[0]);
                tf32_split(v1, vh[1], vl[1]);
                mma_tf32(oacc[nt], phi, vh);
                mma_tf32(oacc[nt], phi, vl);
                mma_tf32(oacc[nt], plo, vh);
            }
        }
    }

    // Epilogue: normalize and store
    const float i0 = 1.0f / l0r, i1 = 1.0f / l1r;
    float* Ap = g_A + head + (size_t)(m0 + wm + gid) * kE;
    #pragma unroll
    for (int nt = 0; nt < 8; nt++) {
        *(float2*)(Ap + nt * 8 + tig * 2) =
            make_float2(oacc[nt][0] * i0, oacc[nt][1] * i0);
        *(float2*)(Ap + 8 * (size_t)kE + nt * 8 + tig * 2) =
            make_float2(oacc[nt][2] * i1, oacc[nt][3] * i1);
    }
}

// ---------------------------------------------------------------------------
// Kernel 3: out[bt,l,e] = sum_h w[h] * attn[bt,h,l,e]
// ---------------------------------------------------------------------------
__global__ __launch_bounds__(256)
void head_reduce(const float* __restrict__ w, float* __restrict__ out)
{
    const int total = kBT * kL * kE / 4;
    int v = blockIdx.x * 256 + threadIdx.x;
    if (v >= total) return;
    int bt = v >> 13;
    int r  = v & 8191;

    const float4* A4 = (const float4*)g_A;
    float4 s = make_float4(0.f, 0.f, 0.f, 0.f);
    #pragma unroll
    for (int h = 0; h < kH; h++) {
        float wh = __ldg(w + h);
        float4 a = A4[((size_t)bt * kH + h) * 8192 + r];
        s.x += wh * a.x;
        s.y += wh * a.y;
        s.z += wh * a.z;
        s.w += wh * a.w;
    }
    ((float4*)out)[v] = s;
}

// ---------------------------------------------------------------------------
extern "C" void kernel_launch(void* const* d_in, const int* in_sizes, int n_in,
                              void* d_out, int out_size)
{
    const float* q   = (const float*)d_in[0];
    const float* k   = (const float*)d_in[1];
    const float* v   = (const float*)d_in[2];
    const float* msk = (const float*)d_in[3];
    const float* Wq  = (const float*)d_in[4];
    const float* Wk  = (const float*)d_in[5];
    const float* Wv  = (const float*)d_in[6];
    const float* wh  = (const float*)d_in[7];
    const float* tau = (const float*)d_in[8];
    const float* del = (const float*)d_in[9];

    static bool attr_set = false;
    if (!attr_set) {
        cudaFuncSetAttribute(proj_mma, cudaFuncAttributeMaxDynamicSharedMemorySize,
                             (int)SMEM_BYTES);
        cudaFuncSetAttribute(attn_mma, cudaFuncAttributeMaxDynamicSharedMemorySize,
                             (int)ATTN_SMEM);
        attr_set = true;
    }

    mask_init<<<1, 1>>>();
    mask_check<<<(kL * kL + 255) / 256, 256>>>(msk);

    transpose_w<<<dim3(16, 16, 3), dim3(32, 8)>>>(Wq, Wk, Wv);
    proj_mma<<<dim3(16, kBT, 3), 256, SMEM_BYTES>>>(q, k, v);
    attn_mma<<<dim3(kL / 128, kH, kBT), 256, ATTN_SMEM>>>(msk, tau, del);
    head_reduce<<<(kBT * kL * kE / 4 + 255) / 256, 256>>>(wh, (float*)d_out);
}

// round 6
// speedup vs baseline: 2.2496x; 1.4469x over previous
#include <cuda_runtime.h>
#include <cstdint>

// Problem constants
namespace {
constexpr int kBT = 32;   // B*T
constexpr int kL  = 512;
constexpr int kD  = 512;
constexpr int kH  = 8;
constexpr int kE  = 64;

// tf32 mma.sync projection GEMM tiling (cp.async 3-stage pipeline)
constexpr int CTA_M = 128;
constexpr int CTA_N = 128;
constexpr int BK    = 32;
constexpr int PSTR  = 36;                 // smem row stride floats (bank = 4*gid+tig)
constexpr int STAGES = 3;
constexpr int STAGE_FLOATS = CTA_M * PSTR;          // 4608 per operand
constexpr uint32_t STAGE_BYTES = STAGE_FLOATS * 4;  // 18432
constexpr uint32_t SMEM_BYTES = STAGES * 2 * STAGE_BYTES;  // 110592

// attention mma tiling
constexpr int QS_STR = 68;
constexpr int KS_STR = 68;
constexpr int VS_STR = 72;
constexpr int SM_QS = 0;
constexpr int SM_KS = 128 * QS_STR;
constexpr int SM_VS = SM_KS + 64 * KS_STR;
constexpr uint32_t ATTN_SMEM = (uint32_t)(SM_VS + 64 * VS_STR) * 4;  // 70656 B
}

// Scratch (device globals: allocation-free per harness rules).
__device__ __align__(16) float g_Q[kBT * kH * kL * kE];
__device__ __align__(16) float g_K[kBT * kH * kL * kE];
__device__ __align__(16) float g_V[kBT * kH * kL * kE];
__device__ __align__(16) float g_A[kBT * kH * kL * kE];
__device__ __align__(16) float g_Wt[3 * kD * kH * kE];   // transposed weights [w][n][k]
__device__ int g_maskones;

__device__ __forceinline__ uint32_t f2tf32(float x) {
    uint32_t r;
    asm("cvt.rna.tf32.f32 %0, %1;" : "=r"(r) : "f"(x));
    return r;
}

__device__ __forceinline__ void mma_tf32(float* c, const uint32_t* a, const uint32_t* b) {
    asm volatile(
        "mma.sync.aligned.m16n8k8.row.col.f32.tf32.tf32.f32 "
        "{%0,%1,%2,%3}, {%4,%5,%6,%7}, {%8,%9}, {%0,%1,%2,%3};"
        : "+f"(c[0]), "+f"(c[1]), "+f"(c[2]), "+f"(c[3])
        : "r"(a[0]), "r"(a[1]), "r"(a[2]), "r"(a[3]), "r"(b[0]), "r"(b[1]));
}

// Split fp32 x into hi (tf32-exact, mantissa-truncated) + lo (tf32-rounded residual).
__device__ __forceinline__ void tf32_split(float x, uint32_t& hi, uint32_t& lo) {
    hi = __float_as_uint(x) & 0xffffe000u;
    lo = f2tf32(x - __uint_as_float(hi));
}

__device__ __forceinline__ uint32_t smem_u32(const void* p) {
    uint32_t a;
    asm("{ .reg .u64 t; cvta.to.shared.u64 t, %1; cvt.u32.u64 %0, t; }" : "=r"(a) : "l"(p));
    return a;
}
__device__ __forceinline__ void cp16(uint32_t dst, const void* src) {
    asm volatile("cp.async.cg.shared.global [%0], [%1], 16;" :: "r"(dst), "l"(src));
}
__device__ __forceinline__ void cp_commit() {
    asm volatile("cp.async.commit_group;" ::: "memory");
}
__device__ __forceinline__ void cp_wait2() {
    asm volatile("cp.async.wait_group 2;" ::: "memory");
}

// ---------------------------------------------------------------------------
// Kernel 0: weight transpose  Wt[w][n][k] = W_w[k][n]   (512x512 each)
// ---------------------------------------------------------------------------
__global__ __launch_bounds__(256)
void transpose_w(const float* __restrict__ Wq, const float* __restrict__ Wk,
                 const float* __restrict__ Wv)
{
    __shared__ float t[32][33];
    const int w = blockIdx.z;
    const float* W = (w == 0) ? Wq : (w == 1) ? Wk : Wv;
    float* Wt = g_Wt + (size_t)w * (kD * kH * kE);
    const int x0 = blockIdx.x * 32, y0 = blockIdx.y * 32;
    const int tx = threadIdx.x, ty = threadIdx.y;
    #pragma unroll
    for (int i = 0; i < 32; i += 8)
        t[ty + i][tx] = W[(size_t)(y0 + ty + i) * 512 + x0 + tx];
    __syncthreads();
    #pragma unroll
    for (int i = 0; i < 32; i += 8)
        Wt[(size_t)(x0 + ty + i) * 512 + y0 + tx] = t[tx][ty + i];
}

// ---------------------------------------------------------------------------
// Mask all-ones detection (deterministic; enables fast path in attn_mma)
// ---------------------------------------------------------------------------
__global__ void mask_init() { g_maskones = 1; }
__global__ __launch_bounds__(256)
void mask_check(const float* __restrict__ mask)
{
    int i = blockIdx.x * 256 + threadIdx.x;
    if (i < kL * kL && __ldg(mask + i) != 1.0f) g_maskones = 0;
}

// ---------------------------------------------------------------------------
// Kernel 1: tf32 mma.sync projection GEMM, cp.async 3-stage pipeline.
// Per (bt, w): C[l, n] = X[l, d] * W[d, n], B = W^T stored [n][k].
// Smem natural row-major [m][k]/[n][k], stride 36 floats -> fragment gathers
// conflict-free (bank = 4*gid + tig). tf32 conversion at fragment load (rna).
// ---------------------------------------------------------------------------
__global__ __launch_bounds__(256, 2)
void proj_mma(const float* __restrict__ Xq, const float* __restrict__ Xk,
              const float* __restrict__ Xv)
{
    extern __shared__ float S[];
    const uint32_t sbase = smem_u32(S);

    const int tid = threadIdx.x;
    const int wid = tid >> 5;
    const int lane = tid & 31;
    const int gid = lane >> 2;
    const int tig = lane & 3;

    const int w  = blockIdx.z;
    const int bt = blockIdx.y;
    const int m0 = (blockIdx.x >> 2) * CTA_M;
    const int n0 = (blockIdx.x & 3) * CTA_N;
    const int wm = (wid >> 2) * 64;
    const int wn = (wid & 3) * 32;

    const float* X  = (w == 0) ? Xq : (w == 1) ? Xk : Xv;
    const float* Wt = g_Wt + (size_t)w * (kD * kH * kE);
    float* out      = (w == 0) ? g_Q : (w == 1) ? g_K : g_V;

    const float* Ag = X + ((size_t)bt * kL + m0) * kD;
    const float* Bg = Wt + (size_t)n0 * kD;

    // cp.async mapping: 1024 16B-chunks per operand per stage, 4 per thread.
    const int crow = tid >> 3;          // +64 per i
    const int ccol = (tid & 7) * 4;     // k-offset in floats (chunk of 4)

    const int NT = kD / BK;  // 16

    // Issue one stage's A+B cp.asyncs (p = K-tile index, st = stage slot)
    auto issue_stage = [&](int p, int st) {
        const uint32_t abase = sbase + (uint32_t)st * 2 * STAGE_BYTES;
        const uint32_t bbase = abase + STAGE_BYTES;
        const float* Agp = Ag + p * BK;
        const float* Bgp = Bg + p * BK;
        #pragma unroll
        for (int i = 0; i < 4; i++) {
            int r = crow + i * 32;
            cp16(abase + (uint32_t)(r * PSTR + ccol) * 4, Agp + (size_t)r * kD + ccol);
            cp16(bbase + (uint32_t)(r * PSTR + ccol) * 4, Bgp + (size_t)r * kD + ccol);
        }
    };

    // Prologue: fill 3 stages
    #pragma unroll
    for (int s = 0; s < STAGES; s++) {
        issue_stage(s, s);
        cp_commit();
    }

    float acc[4][4][4] = {};

    for (int t = 0; t < NT; t++) {
        cp_wait2();          // stage t complete
        __syncthreads();     // visible to all threads

        const int st = t % STAGES;
        const float* As = S + (size_t)st * 2 * STAGE_FLOATS;
        const float* Bs = As + STAGE_FLOATS;

        #pragma unroll
        for (int ks = 0; ks < 4; ks++) {
            const int kk = ks * 8 + tig;
            uint32_t afr[4][4], bfr[4][2];
            #pragma unroll
            for (int mt = 0; mt < 4; mt++) {
                const float* ab = As + (wm + mt * 16 + gid) * PSTR + kk;
                afr[mt][0] = f2tf32(ab[0]);
                afr[mt][1] = f2tf32(ab[8 * PSTR]);
                afr[mt][2] = f2tf32(ab[4]);
                afr[mt][3] = f2tf32(ab[8 * PSTR + 4]);
            }
            #pragma unroll
            for (int nt = 0; nt < 4; nt++) {
                const float* bb = Bs + (wn + nt * 8 + gid) * PSTR + kk;
                bfr[nt][0] = f2tf32(bb[0]);
                bfr[nt][1] = f2tf32(bb[4]);
            }
            #pragma unroll
            for (int mt = 0; mt < 4; mt++)
                #pragma unroll
                for (int nt = 0; nt < 4; nt++)
                    mma_tf32(acc[mt][nt], afr[mt], bfr[nt]);
        }

        __syncthreads();     // all readers done with stage t before overwrite
        if (t + STAGES < NT) issue_stage(t + STAGES, st);
        cp_commit();         // commit (possibly empty) keeps group counting uniform
    }

    // Epilogue: head-major store
    #pragma unroll
    for (int mt = 0; mt < 4; mt++) {
        #pragma unroll
        for (int nt = 0; nt < 4; nt++) {
            const int n = n0 + wn + nt * 8 + tig * 2;
            const int h = n >> 6;
            const int e = n & 63;
            const int l = m0 + wm + mt * 16 + gid;
            float* O = out + (((size_t)(bt * kH + h) * kL) + l) * kE + e;
            *(float2*)O = make_float2(acc[mt][nt][0], acc[mt][nt][1]);
            *(float2*)(O + 8 * (size_t)kE) = make_float2(acc[mt][nt][2], acc[mt][nt][3]);
        }
    }
}

// ---------------------------------------------------------------------------
// Kernel 2: flash attention with tf32x3 mma.sync (unchanged from round 5).
// ---------------------------------------------------------------------------
__global__ __launch_bounds__(256, 2)
void attn_mma(const float* __restrict__ mask,
              const float* __restrict__ tau,
              const float* __restrict__ delta)
{
    extern __shared__ float sm[];
    float* Qs = sm + SM_QS;
    float* Ks = sm + SM_KS;
    float* Vs = sm + SM_VS;

    const int tid  = threadIdx.x;
    const int wid  = tid >> 5;
    const int lane = tid & 31;
    const int gid  = lane >> 2;
    const int tig  = lane & 3;

    const int bt = blockIdx.z, h = blockIdx.y;
    const int m0 = blockIdx.x * 128;
    const int wm = wid * 16;

    const size_t head = (size_t)(bt * kH + h) * (kL * kE);
    const float* Qp = g_Q + head + (size_t)m0 * kE;
    const float* Kp = g_K + head;
    const float* Vp = g_V + head;

    const float sc = 0.125f;
    const float ta = __ldg(tau) * sc;
    const float db = __ldg(delta) * sc;
    const int ones = g_maskones;

    #pragma unroll
    for (int i = 0; i < 8; i++) {
        int idx = tid + i * 256;
        int m = idx >> 4, c = (idx & 15) * 4;
        *(float4*)(Qs + m * QS_STR + c) = *(const float4*)(Qp + m * kE + c);
    }
    __syncthreads();

    float qf[8][4];
    #pragma unroll
    for (int ks = 0; ks < 8; ks++) {
        const float* qb = Qs + (wm + gid) * QS_STR + ks * 8 + tig;
        qf[ks][0] = qb[0];
        qf[ks][1] = qb[8 * QS_STR];
        qf[ks][2] = qb[4];
        qf[ks][3] = qb[8 * QS_STR + 4];
    }

    float oacc[8][4] = {};
    float m0r = -1e30f, m1r = -1e30f, l0r = 0.f, l1r = 0.f;

    for (int s0 = 0; s0 < kL; s0 += 64) {
        if (s0) __syncthreads();

        #pragma unroll
        for (int i = 0; i < 4; i++) {
            int idx = tid + i * 256;
            int s = idx >> 4, c = (idx & 15) * 4;
            *(float4*)(Ks + s * KS_STR + c) = *(const float4*)(Kp + (s0 + s) * kE + c);
            *(float4*)(Vs + s * VS_STR + c) = *(const float4*)(Vp + (s0 + s) * kE + c);
        }
        __syncthreads();

        float sacc[8][4] = {};
        #pragma unroll
        for (int ks = 0; ks < 8; ks++) {
            uint32_t qhi[4], qlo[4];
            #pragma unroll
            for (int j = 0; j < 4; j++) tf32_split(qf[ks][j], qhi[j], qlo[j]);
            #pragma unroll
            for (int nt = 0; nt < 8; nt++) {
                const float* kb = Ks + (nt * 8 + gid) * KS_STR + ks * 8 + tig;
                float k0 = kb[0], k1 = kb[4];
                uint32_t kh[2], kl[2];
                tf32_split(k0, kh[0], kl[0]);
                tf32_split(k1, kh[1], kl[1]);
                mma_tf32(sacc[nt], qhi, kh);
                mma_tf32(sacc[nt], qhi, kl);
                mma_tf32(sacc[nt], qlo, kh);
            }
        }

        if (ones) {
            #pragma unroll
            for (int nt = 0; nt < 8; nt++)
                #pragma unroll
                for (int j = 0; j < 4; j++)
                    sacc[nt][j] = fmaf(sacc[nt][j], ta, db);
        } else {
            const float* mr0 = mask + (size_t)(m0 + wm + gid) * kL + s0;
            const float* mr1 = mr0 + 8 * (size_t)kL;
            #pragma unroll
            for (int nt = 0; nt < 8; nt++) {
                float2 mv0 = __ldg((const float2*)(mr0 + nt * 8 + tig * 2));
                float2 mv1 = __ldg((const float2*)(mr1 + nt * 8 + tig * 2));
                sacc[nt][0] = fmaf(sacc[nt][0], ta, db) * mv0.x;
                sacc[nt][1] = fmaf(sacc[nt][1], ta, db) * mv0.y;
                sacc[nt][2] = fmaf(sacc[nt][2], ta, db) * mv1.x;
                sacc[nt][3] = fmaf(sacc[nt][3], ta, db) * mv1.y;
            }
        }

        float tm0 = -1e30f, tm1 = -1e30f;
        #pragma unroll
        for (int nt = 0; nt < 8; nt++) {
            tm0 = fmaxf(tm0, fmaxf(sacc[nt][0], sacc[nt][1]));
            tm1 = fmaxf(tm1, fmaxf(sacc[nt][2], sacc[nt][3]));
        }
        tm0 = fmaxf(tm0, __shfl_xor_sync(0xffffffffu, tm0, 1));
        tm0 = fmaxf(tm0, __shfl_xor_sync(0xffffffffu, tm0, 2));
        tm1 = fmaxf(tm1, __shfl_xor_sync(0xffffffffu, tm1, 1));
        tm1 = fmaxf(tm1, __shfl_xor_sync(0xffffffffu, tm1, 2));

        float mn0 = fmaxf(m0r, tm0), mn1 = fmaxf(m1r, tm1);
        float c0 = __expf(m0r - mn0), c1 = __expf(m1r - mn1);
        m0r = mn0; m1r = mn1;

        float rs0 = 0.f, rs1 = 0.f;
        float* pb0 = Qs + (wm + gid) * QS_STR + tig * 2;
        float* pb1 = pb0 + 8 * QS_STR;
        #pragma unroll
        for (int nt = 0; nt < 8; nt++) {
            float p0 = __expf(sacc[nt][0] - mn0);
            float p1 = __expf(sacc[nt][1] - mn0);
            float p2 = __expf(sacc[nt][2] - mn1);
            float p3 = __expf(sacc[nt][3] - mn1);
            rs0 += p0 + p1;
            rs1 += p2 + p3;
            pb0[nt * 8 + 0] = p0;
            pb0[nt * 8 + 1] = p1;
            pb1[nt * 8 + 0] = p2;
            pb1[nt * 8 + 1] = p3;
            oacc[nt][0] *= c0; oacc[nt][1] *= c0;
            oacc[nt][2] *= c1; oacc[nt][3] *= c1;
        }
        rs0 += __shfl_xor_sync(0xffffffffu, rs0, 1);
        rs0 += __shfl_xor_sync(0xffffffffu, rs0, 2);
        rs1 += __shfl_xor_sync(0xffffffffu, rs1, 1);
        rs1 += __shfl_xor_sync(0xffffffffu, rs1, 2);
        l0r = l0r * c0 + rs0;
        l1r = l1r * c1 + rs1;

        __syncwarp();

        #pragma unroll
        for (int ks = 0; ks < 8; ks++) {
            const float* pf = Qs + (wm + gid) * QS_STR + ks * 8 + tig;
            float p0 = pf[0], p1 = pf[8 * QS_STR], p2 = pf[4], p3 = pf[8 * QS_STR + 4];
            uint32_t phi[4], plo[4];
            tf32_split(p0, phi[0], plo[0]);
            tf32_split(p1, phi[1], plo[1]);
            tf32_split(p2, phi[2], plo[2]);
            tf32_split(p3, phi[3], plo[3]);
            #pragma unroll
            for (int nt = 0; nt < 8; nt++) {
                const float* vb = Vs + (ks * 8 + tig) * VS_STR + nt * 8 + gid;
                float v0 = vb[0], v1 = vb[4 * VS_STR];
                uint32_t vh[2], vl[2];
                tf32_split(v0, vh[0], vl[0]);
                tf32_split(v1, vh[1], vl[1]);
                mma_tf32(oacc[nt], phi, vh);
                mma_tf32(oacc[nt], phi, vl);
                mma_tf32(oacc[nt], plo, vh);
            }
        }
    }

    const float i0 = 1.0f / l0r, i1 = 1.0f / l1r;
    float* Ap = g_A + head + (size_t)(m0 + wm + gid) * kE;
    #pragma unroll
    for (int nt = 0; nt < 8; nt++) {
        *(float2*)(Ap + nt * 8 + tig * 2) =
            make_float2(oacc[nt][0] * i0, oacc[nt][1] * i0);
        *(float2*)(Ap + 8 * (size_t)kE + nt * 8 + tig * 2) =
            make_float2(oacc[nt][2] * i1, oacc[nt][3] * i1);
    }
}

// ---------------------------------------------------------------------------
// Kernel 3: out[bt,l,e] = sum_h w[h] * attn[bt,h,l,e]
// ---------------------------------------------------------------------------
__global__ __launch_bounds__(256)
void head_reduce(const float* __restrict__ w, float* __restrict__ out)
{
    const int total = kBT * kL * kE / 4;
    int v = blockIdx.x * 256 + threadIdx.x;
    if (v >= total) return;
    int bt = v >> 13;
    int r  = v & 8191;

    const float4* A4 = (const float4*)g_A;
    float4 s = make_float4(0.f, 0.f, 0.f, 0.f);
    #pragma unroll
    for (int h = 0; h < kH; h++) {
        float wh = __ldg(w + h);
        float4 a = A4[((size_t)bt * kH + h) * 8192 + r];
        s.x += wh * a.x;
        s.y += wh * a.y;
        s.z += wh * a.z;
        s.w += wh * a.w;
    }
    ((float4*)out)[v] = s;
}

// ---------------------------------------------------------------------------
extern "C" void kernel_launch(void* const* d_in, const int* in_sizes, int n_in,
                              void* d_out, int out_size)
{
    const float* q   = (const float*)d_in[0];
    const float* k   = (const float*)d_in[1];
    const float* v   = (const float*)d_in[2];
    const float* msk = (const float*)d_in[3];
    const float* Wq  = (const float*)d_in[4];
    const float* Wk  = (const float*)d_in[5];
    const float* Wv  = (const float*)d_in[6];
    const float* wh  = (const float*)d_in[7];
    const float* tau = (const float*)d_in[8];
    const float* del = (const float*)d_in[9];

    static bool attr_set = false;
    if (!attr_set) {
        cudaFuncSetAttribute(proj_mma, cudaFuncAttributeMaxDynamicSharedMemorySize,
                             (int)SMEM_BYTES);
        cudaFuncSetAttribute(attn_mma, cudaFuncAttributeMaxDynamicSharedMemorySize,
                             (int)ATTN_SMEM);
        attr_set = true;
    }

    mask_init<<<1, 1>>>();
    mask_check<<<(kL * kL + 255) / 256, 256>>>(msk);

    transpose_w<<<dim3(16, 16, 3), dim3(32, 8)>>>(Wq, Wk, Wv);
    proj_mma<<<dim3(16, kBT, 3), 256, SMEM_BYTES>>>(q, k, v);
    attn_mma<<<dim3(kL / 128, kH, kBT), 256, ATTN_SMEM>>>(msk, tau, del);
    head_reduce<<<(kBT * kL * kE / 4 + 255) / 256, 256>>>(wh, (float*)d_out);
}

// round 7
// speedup vs baseline: 3.0592x; 1.3599x over previous
#include <cuda_runtime.h>
#include <cstdint>

// Problem constants
namespace {
constexpr int kBT = 32;   // B*T
constexpr int kL  = 512;
constexpr int kD  = 512;
constexpr int kH  = 8;
constexpr int kE  = 64;

// tf32 mma.sync projection GEMM tiling (cp.async 3-stage pipeline)
constexpr int CTA_M = 128;
constexpr int CTA_N = 128;
constexpr int BK    = 32;
constexpr int PSTR  = 36;
constexpr int STAGES = 3;
constexpr int STAGE_FLOATS = CTA_M * PSTR;
constexpr uint32_t STAGE_BYTES = STAGE_FLOATS * 4;
constexpr uint32_t SMEM_BYTES = STAGES * 2 * STAGE_BYTES;  // 110592

// attention bf16x3 tiling: packed u32 tiles, stride 36 (bank 4*gid+tig)
constexpr int SM_KHL = 0;          // Khl [64][36]
constexpr int SM_KLO = 2304;       // Klo [64][36]
constexpr int SM_VHL = 4608;       // Vthl [e=64][sp 36]
constexpr int SM_VLO = 6912;
constexpr int SM_PHL = 9216;       // Phl [128][36]
constexpr int SM_PLO = 13824;
constexpr uint32_t ATTN_SMEM = 18432u * 4;  // 73728 B
}

// Scratch (device globals: allocation-free per harness rules).
__device__ __align__(16) float g_Q[kBT * kH * kL * kE];
__device__ __align__(16) float g_K[kBT * kH * kL * kE];
__device__ __align__(16) float g_V[kBT * kH * kL * kE];
__device__ __align__(16) float g_A[kBT * kH * kL * kE];
__device__ __align__(16) float g_Wt[3 * kD * kH * kE];
__device__ int g_maskones;

__device__ __forceinline__ uint32_t f2tf32(float x) {
    uint32_t r;
    asm("cvt.rna.tf32.f32 %0, %1;" : "=r"(r) : "f"(x));
    return r;
}

__device__ __forceinline__ void mma_tf32(float* c, const uint32_t* a, const uint32_t* b) {
    asm volatile(
        "mma.sync.aligned.m16n8k8.row.col.f32.tf32.tf32.f32 "
        "{%0,%1,%2,%3}, {%4,%5,%6,%7}, {%8,%9}, {%0,%1,%2,%3};"
        : "+f"(c[0]), "+f"(c[1]), "+f"(c[2]), "+f"(c[3])
        : "r"(a[0]), "r"(a[1]), "r"(a[2]), "r"(a[3]), "r"(b[0]), "r"(b[1]));
}

__device__ __forceinline__ void mma_bf16(float* c, const uint32_t* a, const uint32_t* b) {
    asm volatile(
        "mma.sync.aligned.m16n8k16.row.col.f32.bf16.bf16.f32 "
        "{%0,%1,%2,%3}, {%4,%5,%6,%7}, {%8,%9}, {%0,%1,%2,%3};"
        : "+f"(c[0]), "+f"(c[1]), "+f"(c[2]), "+f"(c[3])
        : "r"(a[0]), "r"(a[1]), "r"(a[2]), "r"(a[3]), "r"(b[0]), "r"(b[1]));
}

// round-to-nearest-even bf16, returned as fp32
__device__ __forceinline__ float bf16hi(float x) {
    uint32_t u = __float_as_uint(x);
    u = (u + 0x7fffu + ((u >> 16) & 1u)) & 0xffff0000u;
    return __uint_as_float(u);
}
// pack two floats -> bf16x2 (e0 = low half = even-k element)
__device__ __forceinline__ uint32_t packbf(float e0, float e1) {
    uint32_t r;
    asm("cvt.rn.bf16x2.f32 %0, %1, %2;" : "=r"(r) : "f"(e1), "f"(e0));
    return r;
}
// split pair (x0 even-k, x1 odd-k) into packed hi + packed lo residual
__device__ __forceinline__ void split2(float x0, float x1, uint32_t& hi, uint32_t& lo) {
    float h0 = bf16hi(x0), h1 = bf16hi(x1);
    hi = packbf(h0, h1);
    lo = packbf(x0 - h0, x1 - h1);
}
__device__ __forceinline__ int vtix(int e, int sp) {
    return e * 36 + (sp ^ ((e >> 3) & 3));
}

__device__ __forceinline__ uint32_t smem_u32p(const void* p) {
    uint32_t a;
    asm("{ .reg .u64 t; cvta.to.shared.u64 t, %1; cvt.u32.u64 %0, t; }" : "=r"(a) : "l"(p));
    return a;
}
__device__ __forceinline__ void cp16(uint32_t dst, const void* src) {
    asm volatile("cp.async.cg.shared.global [%0], [%1], 16;" :: "r"(dst), "l"(src));
}
__device__ __forceinline__ void cp_commit() {
    asm volatile("cp.async.commit_group;" ::: "memory");
}
__device__ __forceinline__ void cp_wait2() {
    asm volatile("cp.async.wait_group 2;" ::: "memory");
}

// ---------------------------------------------------------------------------
// Kernel 0: weight transpose  Wt[w][n][k] = W_w[k][n]
// ---------------------------------------------------------------------------
__global__ __launch_bounds__(256)
void transpose_w(const float* __restrict__ Wq, const float* __restrict__ Wk,
                 const float* __restrict__ Wv)
{
    __shared__ float t[32][33];
    const int w = blockIdx.z;
    const float* W = (w == 0) ? Wq : (w == 1) ? Wk : Wv;
    float* Wt = g_Wt + (size_t)w * (kD * kH * kE);
    const int x0 = blockIdx.x * 32, y0 = blockIdx.y * 32;
    const int tx = threadIdx.x, ty = threadIdx.y;
    #pragma unroll
    for (int i = 0; i < 32; i += 8)
        t[ty + i][tx] = W[(size_t)(y0 + ty + i) * 512 + x0 + tx];
    __syncthreads();
    #pragma unroll
    for (int i = 0; i < 32; i += 8)
        Wt[(size_t)(x0 + ty + i) * 512 + y0 + tx] = t[tx][ty + i];
}

// ---------------------------------------------------------------------------
// Mask all-ones detection
// ---------------------------------------------------------------------------
__global__ void mask_init() { g_maskones = 1; }
__global__ __launch_bounds__(256)
void mask_check(const float* __restrict__ mask)
{
    int i = blockIdx.x * 256 + threadIdx.x;
    if (i < kL * kL && __ldg(mask + i) != 1.0f) g_maskones = 0;
}

// ---------------------------------------------------------------------------
// Kernel 1: tf32 mma.sync projection GEMM, cp.async 3-stage (round-6, passing)
// ---------------------------------------------------------------------------
__global__ __launch_bounds__(256, 2)
void proj_mma(const float* __restrict__ Xq, const float* __restrict__ Xk,
              const float* __restrict__ Xv)
{
    extern __shared__ float S[];
    const uint32_t sbase = smem_u32p(S);

    const int tid = threadIdx.x;
    const int wid = tid >> 5;
    const int lane = tid & 31;
    const int gid = lane >> 2;
    const int tig = lane & 3;

    const int w  = blockIdx.z;
    const int bt = blockIdx.y;
    const int m0 = (blockIdx.x >> 2) * CTA_M;
    const int n0 = (blockIdx.x & 3) * CTA_N;
    const int wm = (wid >> 2) * 64;
    const int wn = (wid & 3) * 32;

    const float* X  = (w == 0) ? Xq : (w == 1) ? Xk : Xv;
    const float* Wt = g_Wt + (size_t)w * (kD * kH * kE);
    float* out      = (w == 0) ? g_Q : (w == 1) ? g_K : g_V;

    const float* Ag = X + ((size_t)bt * kL + m0) * kD;
    const float* Bg = Wt + (size_t)n0 * kD;

    const int crow = tid >> 3;
    const int ccol = (tid & 7) * 4;
    const int NT = kD / BK;

    auto issue_stage = [&](int p, int st) {
        const uint32_t abase = sbase + (uint32_t)st * 2 * STAGE_BYTES;
        const uint32_t bbase = abase + STAGE_BYTES;
        const float* Agp = Ag + p * BK;
        const float* Bgp = Bg + p * BK;
        #pragma unroll
        for (int i = 0; i < 4; i++) {
            int r = crow + i * 32;
            cp16(abase + (uint32_t)(r * PSTR + ccol) * 4, Agp + (size_t)r * kD + ccol);
            cp16(bbase + (uint32_t)(r * PSTR + ccol) * 4, Bgp + (size_t)r * kD + ccol);
        }
    };

    #pragma unroll
    for (int s = 0; s < STAGES; s++) {
        issue_stage(s, s);
        cp_commit();
    }

    float acc[4][4][4] = {};

    for (int t = 0; t < NT; t++) {
        cp_wait2();
        __syncthreads();

        const int st = t % STAGES;
        const float* As = S + (size_t)st * 2 * STAGE_FLOATS;
        const float* Bs = As + STAGE_FLOATS;

        #pragma unroll
        for (int ks = 0; ks < 4; ks++) {
            const int kk = ks * 8 + tig;
            uint32_t afr[4][4], bfr[4][2];
            #pragma unroll
            for (int mt = 0; mt < 4; mt++) {
                const float* ab = As + (wm + mt * 16 + gid) * PSTR + kk;
                afr[mt][0] = f2tf32(ab[0]);
                afr[mt][1] = f2tf32(ab[8 * PSTR]);
                afr[mt][2] = f2tf32(ab[4]);
                afr[mt][3] = f2tf32(ab[8 * PSTR + 4]);
            }
            #pragma unroll
            for (int nt = 0; nt < 4; nt++) {
                const float* bb = Bs + (wn + nt * 8 + gid) * PSTR + kk;
                bfr[nt][0] = f2tf32(bb[0]);
                bfr[nt][1] = f2tf32(bb[4]);
            }
            #pragma unroll
            for (int mt = 0; mt < 4; mt++)
                #pragma unroll
                for (int nt = 0; nt < 4; nt++)
                    mma_tf32(acc[mt][nt], afr[mt], bfr[nt]);
        }

        __syncthreads();
        if (t + STAGES < NT) issue_stage(t + STAGES, st);
        cp_commit();
    }

    #pragma unroll
    for (int mt = 0; mt < 4; mt++) {
        #pragma unroll
        for (int nt = 0; nt < 4; nt++) {
            const int n = n0 + wn + nt * 8 + tig * 2;
            const int h = n >> 6;
            const int e = n & 63;
            const int l = m0 + wm + mt * 16 + gid;
            float* O = out + (((size_t)(bt * kH + h) * kL) + l) * kE + e;
            *(float2*)O = make_float2(acc[mt][nt][0], acc[mt][nt][1]);
            *(float2*)(O + 8 * (size_t)kE) = make_float2(acc[mt][nt][2], acc[mt][nt][3]);
        }
    }
}

// ---------------------------------------------------------------------------
// Kernel 2: flash attention, bf16x3 m16n8k16 (fp32-equivalent accuracy).
// CTA = 128 q-rows, 8 warps x 16 rows, s-tiles of 64.
// K/V converted ONCE per CTA per tile into packed bf16 hi/lo smem tiles:
//   Khl/Klo [s][dpair] stride 36 (conflict-free frag gathers)
//   Vthl/Vtlo [e][spair] stride 36 with sp ^ ((e>>3)&3) swizzle
// P packed at softmax store (lanes own s-pairs = A-fragment layout).
// Q fragments loaded from gmem into 32 packed registers.
// ---------------------------------------------------------------------------
__global__ __launch_bounds__(256, 2)
void attn_mma(const float* __restrict__ mask,
              const float* __restrict__ tau,
              const float* __restrict__ delta)
{
    extern __shared__ uint32_t smu[];
    uint32_t* Khl = smu + SM_KHL;
    uint32_t* Klo = smu + SM_KLO;
    uint32_t* Vthl = smu + SM_VHL;
    uint32_t* Vtlo = smu + SM_VLO;
    uint32_t* Phl = smu + SM_PHL;
    uint32_t* Plo = smu + SM_PLO;

    const int tid  = threadIdx.x;
    const int wid  = tid >> 5;
    const int lane = tid & 31;
    const int gid  = lane >> 2;
    const int tig  = lane & 3;

    const int bt = blockIdx.z, h = blockIdx.y;
    const int m0 = blockIdx.x * 128;
    const int wm = wid * 16;

    const size_t head = (size_t)(bt * kH + h) * (kL * kE);
    const float* Qp = g_Q + head + (size_t)m0 * kE;
    const float* Kp = g_K + head;
    const float* Vp = g_V + head;

    const float sc = 0.125f;
    const float ta = __ldg(tau) * sc;
    const float db = __ldg(delta) * sc;
    const int ones = g_maskones;

    // Q fragments direct from gmem: 4 k16-chunks, hi+lo packed (32 regs)
    uint32_t qh[4][4], ql[4][4];
    {
        const float* Qr0 = Qp + (size_t)(wm + gid) * kE;
        const float* Qr1 = Qp + (size_t)(wm + gid + 8) * kE;
        #pragma unroll
        for (int ks = 0; ks < 4; ks++) {
            const int b = ks * 16 + 2 * tig;
            float2 x0 = *(const float2*)(Qr0 + b);
            float2 x1 = *(const float2*)(Qr1 + b);
            float2 x2 = *(const float2*)(Qr0 + b + 8);
            float2 x3 = *(const float2*)(Qr1 + b + 8);
            split2(x0.x, x0.y, qh[ks][0], ql[ks][0]);
            split2(x1.x, x1.y, qh[ks][1], ql[ks][1]);
            split2(x2.x, x2.y, qh[ks][2], ql[ks][2]);
            split2(x3.x, x3.y, qh[ks][3], ql[ks][3]);
        }
    }

    float oacc[8][4] = {};
    float m0r = -1e30f, m1r = -1e30f, l0r = 0.f, l1r = 0.f;

    for (int s0 = 0; s0 < kL; s0 += 64) {
        if (s0) __syncthreads();   // prev tile's readers done before overwrite

        // K convert: [64][64] f32 -> Khl/Klo packed (16 elems/thread)
        #pragma unroll
        for (int i = 0; i < 4; i++) {
            int idx = tid + i * 256;
            int s = idx >> 4, c = (idx & 15) * 4;
            float4 kv = *(const float4*)(Kp + (size_t)(s0 + s) * kE + c);
            uint32_t h0, l0, h1, l1;
            split2(kv.x, kv.y, h0, l0);
            split2(kv.z, kv.w, h1, l1);
            int off = s * 36 + c / 2;
            *(uint2*)(Khl + off) = make_uint2(h0, h1);
            *(uint2*)(Klo + off) = make_uint2(l0, l1);
        }
        // V convert transposed-packed: cell (e, sp) = V[2sp..2sp+1][e]
        #pragma unroll
        for (int i = 0; i < 4; i++) {
            int idx = tid + i * 256;
            int sp = idx >> 5, e = (idx & 31) * 2;
            const float* vb = Vp + (size_t)(s0 + 2 * sp) * kE + e;
            float2 v0 = *(const float2*)vb;
            float2 v1 = *(const float2*)(vb + kE);
            uint32_t h0, l0, h1, l1;
            split2(v0.x, v1.x, h0, l0);
            split2(v0.y, v1.y, h1, l1);
            Vthl[vtix(e, sp)] = h0;
            Vtlo[vtix(e, sp)] = l0;
            Vthl[vtix(e + 1, sp)] = h1;
            Vtlo[vtix(e + 1, sp)] = l1;
        }
        __syncthreads();

        // ---- S = Q K^T, bf16x3 ----
        float sacc[8][4] = {};
        #pragma unroll
        for (int ks = 0; ks < 4; ks++) {
            #pragma unroll
            for (int nt = 0; nt < 8; nt++) {
                const uint32_t* kb = Khl + (nt * 8 + gid) * 36 + ks * 8 + tig;
                const uint32_t* kb2 = Klo + (nt * 8 + gid) * 36 + ks * 8 + tig;
                uint32_t bh[2] = { kb[0], kb[4] };
                uint32_t bl[2] = { kb2[0], kb2[4] };
                mma_bf16(sacc[nt], qh[ks], bh);
                mma_bf16(sacc[nt], qh[ks], bl);
                mma_bf16(sacc[nt], ql[ks], bh);
            }
        }

        // ---- scale (+mask) + online softmax ----
        if (ones) {
            #pragma unroll
            for (int nt = 0; nt < 8; nt++)
                #pragma unroll
                for (int j = 0; j < 4; j++)
                    sacc[nt][j] = fmaf(sacc[nt][j], ta, db);
        } else {
            const float* mr0 = mask + (size_t)(m0 + wm + gid) * kL + s0;
            const float* mr1 = mr0 + 8 * (size_t)kL;
            #pragma unroll
            for (int nt = 0; nt < 8; nt++) {
                float2 mv0 = __ldg((const float2*)(mr0 + nt * 8 + tig * 2));
                float2 mv1 = __ldg((const float2*)(mr1 + nt * 8 + tig * 2));
                sacc[nt][0] = fmaf(sacc[nt][0], ta, db) * mv0.x;
                sacc[nt][1] = fmaf(sacc[nt][1], ta, db) * mv0.y;
                sacc[nt][2] = fmaf(sacc[nt][2], ta, db) * mv1.x;
                sacc[nt][3] = fmaf(sacc[nt][3], ta, db) * mv1.y;
            }
        }

        float tm0 = -1e30f, tm1 = -1e30f;
        #pragma unroll
        for (int nt = 0; nt < 8; nt++) {
            tm0 = fmaxf(tm0, fmaxf(sacc[nt][0], sacc[nt][1]));
            tm1 = fmaxf(tm1, fmaxf(sacc[nt][2], sacc[nt][3]));
        }
        tm0 = fmaxf(tm0, __shfl_xor_sync(0xffffffffu, tm0, 1));
        tm0 = fmaxf(tm0, __shfl_xor_sync(0xffffffffu, tm0, 2));
        tm1 = fmaxf(tm1, __shfl_xor_sync(0xffffffffu, tm1, 1));
        tm1 = fmaxf(tm1, __shfl_xor_sync(0xffffffffu, tm1, 2));

        float mn0 = fmaxf(m0r, tm0), mn1 = fmaxf(m1r, tm1);
        float c0 = __expf(m0r - mn0), c1 = __expf(m1r - mn1);
        m0r = mn0; m1r = mn1;

        float rs0 = 0.f, rs1 = 0.f;
        const int pr0 = (wm + gid) * 36 + tig;
        const int pr1 = pr0 + 8 * 36;
        #pragma unroll
        for (int nt = 0; nt < 8; nt++) {
            float p0 = __expf(sacc[nt][0] - mn0);
            float p1 = __expf(sacc[nt][1] - mn0);
            float p2 = __expf(sacc[nt][2] - mn1);
            float p3 = __expf(sacc[nt][3] - mn1);
            rs0 += p0 + p1;
            rs1 += p2 + p3;
            uint32_t hh, ll;
            split2(p0, p1, hh, ll);
            Phl[pr0 + nt * 4] = hh;
            Plo[pr0 + nt * 4] = ll;
            split2(p2, p3, hh, ll);
            Phl[pr1 + nt * 4] = hh;
            Plo[pr1 + nt * 4] = ll;
            oacc[nt][0] *= c0; oacc[nt][1] *= c0;
            oacc[nt][2] *= c1; oacc[nt][3] *= c1;
        }
        rs0 += __shfl_xor_sync(0xffffffffu, rs0, 1);
        rs0 += __shfl_xor_sync(0xffffffffu, rs0, 2);
        rs1 += __shfl_xor_sync(0xffffffffu, rs1, 1);
        rs1 += __shfl_xor_sync(0xffffffffu, rs1, 2);
        l0r = l0r * c0 + rs0;
        l1r = l1r * c1 + rs1;

        __syncwarp();   // this warp's P rows visible to its own lanes

        // ---- O += P V, bf16x3 ----
        #pragma unroll
        for (int ks = 0; ks < 4; ks++) {
            const int pb0 = (wm + gid) * 36 + ks * 8 + tig;
            const int pb1 = pb0 + 8 * 36;
            uint32_t ah[4] = { Phl[pb0], Phl[pb1], Phl[pb0 + 4], Phl[pb1 + 4] };
            uint32_t al[4] = { Plo[pb0], Plo[pb1], Plo[pb0 + 4], Plo[pb1 + 4] };
            #pragma unroll
            for (int nt = 0; nt < 8; nt++) {
                const int e = nt * 8 + gid;
                const int v0 = vtix(e, ks * 8 + tig);
                const int v1 = vtix(e, ks * 8 + tig + 4);
                uint32_t bh[2] = { Vthl[v0], Vthl[v1] };
                uint32_t bl[2] = { Vtlo[v0], Vtlo[v1] };
                mma_bf16(oacc[nt], ah, bh);
                mma_bf16(oacc[nt], ah, bl);
                mma_bf16(oacc[nt], al, bh);
            }
        }
    }

    // Epilogue: normalize and store
    const float i0 = 1.0f / l0r, i1 = 1.0f / l1r;
    float* Ap = g_A + head + (size_t)(m0 + wm + gid) * kE;
    #pragma unroll
    for (int nt = 0; nt < 8; nt++) {
        *(float2*)(Ap + nt * 8 + tig * 2) =
            make_float2(oacc[nt][0] * i0, oacc[nt][1] * i0);
        *(float2*)(Ap + 8 * (size_t)kE + nt * 8 + tig * 2) =
            make_float2(oacc[nt][2] * i1, oacc[nt][3] * i1);
    }
}

// ---------------------------------------------------------------------------
// Kernel 3: out[bt,l,e] = sum_h w[h] * attn[bt,h,l,e]
// ---------------------------------------------------------------------------
__global__ __launch_bounds__(256)
void head_reduce(const float* __restrict__ w, float* __restrict__ out)
{
    const int total = kBT * kL * kE / 4;
    int v = blockIdx.x * 256 + threadIdx.x;
    if (v >= total) return;
    int bt = v >> 13;
    int r  = v & 8191;

    const float4* A4 = (const float4*)g_A;
    float4 s = make_float4(0.f, 0.f, 0.f, 0.f);
    #pragma unroll
    for (int h = 0; h < kH; h++) {
        float wh = __ldg(w + h);
        float4 a = A4[((size_t)bt * kH + h) * 8192 + r];
        s.x += wh * a.x;
        s.y += wh * a.y;
        s.z += wh * a.z;
        s.w += wh * a.w;
    }
    ((float4*)out)[v] = s;
}

// ---------------------------------------------------------------------------
extern "C" void kernel_launch(void* const* d_in, const int* in_sizes, int n_in,
                              void* d_out, int out_size)
{
    const float* q   = (const float*)d_in[0];
    const float* k   = (const float*)d_in[1];
    const float* v   = (const float*)d_in[2];
    const float* msk = (const float*)d_in[3];
    const float* Wq  = (const float*)d_in[4];
    const float* Wk  = (const float*)d_in[5];
    const float* Wv  = (const float*)d_in[6];
    const float* wh  = (const float*)d_in[7];
    const float* tau = (const float*)d_in[8];
    const float* del = (const float*)d_in[9];

    static bool attr_set = false;
    if (!attr_set) {
        cudaFuncSetAttribute(proj_mma, cudaFuncAttributeMaxDynamicSharedMemorySize,
                             (int)SMEM_BYTES);
        cudaFuncSetAttribute(attn_mma, cudaFuncAttributeMaxDynamicSharedMemorySize,
                             (int)ATTN_SMEM);
        attr_set = true;
    }

    mask_init<<<1, 1>>>();
    mask_check<<<(kL * kL + 255) / 256, 256>>>(msk);

    transpose_w<<<dim3(16, 16, 3), dim3(32, 8)>>>(Wq, Wk, Wv);
    proj_mma<<<dim3(16, kBT, 3), 256, SMEM_BYTES>>>(q, k, v);
    attn_mma<<<dim3(kL / 128, kH, kBT), 256, ATTN_SMEM>>>(msk, tau, del);
    head_reduce<<<(kBT * kL * kE / 4 + 255) / 256, 256>>>(wh, (float*)d_out);
}